// round 4
// baseline (speedup 1.0000x reference)
#include <cuda_runtime.h>

// Problem: B=2, T=2048, C=768, H=12, D=64
// Reference pipeline (with faithful source bug q := rope(v)):
//   qkv = x @ W_att ; k = qkv[:, :768], v = qkv[:, 1536:2304]  (q chunk UNUSED)
//   K = rope(k), Q = rope(v), V = v      (per-head, [B,H,T,D])
//   O = causal_softmax(Q K^T / 8) V
//   out = O(merged) @ W_proj + b_proj

#define T_ 2048
#define C_ 768
#define H_ 12
#define D_ 64
#define B_ 2

// Scratch (device globals: allocation-guard safe)
__device__ float g_kv[4096 * 1536];               // [B*T, 2C]: k chunk | v chunk
__device__ float g_Q [B_ * H_ * T_ * D_];
__device__ float g_K [B_ * H_ * T_ * D_];
__device__ float g_V [B_ * H_ * T_ * D_];
__device__ float g_O [B_ * H_ * T_ * D_];

// ---------------------------------------------------------------------------
// QKV GEMM (k and v chunks only): g_kv[M=4096, N=1536] = x[4096,768] @ W_att cols
// logical col n -> W_att col (n < 768 ? n : n + 768)
// ---------------------------------------------------------------------------
__global__ __launch_bounds__(256) void gemm_qkv(const float* __restrict__ A,
                                                const float* __restrict__ W) {
    __shared__ float As[16][128];   // transposed A tile: As[k][m]
    __shared__ float Bs[16][128];
    const int tid = threadIdx.x;
    const int tx = tid & 15, ty = tid >> 4;
    const int row0 = blockIdx.y * 128;
    const int col0 = blockIdx.x * 128;
    const int wcol0 = (col0 < 768) ? col0 : col0 + 768;

    float acc[8][8];
#pragma unroll
    for (int i = 0; i < 8; i++)
#pragma unroll
        for (int j = 0; j < 8; j++) acc[i][j] = 0.0f;

    for (int k0 = 0; k0 < 768; k0 += 16) {
#pragma unroll
        for (int it = 0; it < 2; it++) {
            int f = tid + it * 256;          // 0..511 float4s of the A tile
            int r = f >> 2, c4 = (f & 3) << 2;
            float4 a = *(const float4*)(A + (row0 + r) * 768 + k0 + c4);
            As[c4 + 0][r] = a.x; As[c4 + 1][r] = a.y;
            As[c4 + 2][r] = a.z; As[c4 + 3][r] = a.w;
        }
#pragma unroll
        for (int it = 0; it < 2; it++) {
            int f = tid + it * 256;
            int r = f >> 5, c4 = (f & 31) << 2;
            *(float4*)(&Bs[r][c4]) =
                *(const float4*)(W + (k0 + r) * 2304 + wcol0 + c4);
        }
        __syncthreads();
#pragma unroll
        for (int k = 0; k < 16; k++) {
            float ra[8], rb[8];
            *(float4*)(ra)     = *(const float4*)(&As[k][ty * 8]);
            *(float4*)(ra + 4) = *(const float4*)(&As[k][ty * 8 + 4]);
            *(float4*)(rb)     = *(const float4*)(&Bs[k][tx * 8]);
            *(float4*)(rb + 4) = *(const float4*)(&Bs[k][tx * 8 + 4]);
#pragma unroll
            for (int i = 0; i < 8; i++)
#pragma unroll
                for (int j = 0; j < 8; j++) acc[i][j] += ra[i] * rb[j];
        }
        __syncthreads();
    }
#pragma unroll
    for (int i = 0; i < 8; i++) {
        float4 v0 = make_float4(acc[i][0], acc[i][1], acc[i][2], acc[i][3]);
        float4 v1 = make_float4(acc[i][4], acc[i][5], acc[i][6], acc[i][7]);
        float* p = g_kv + (row0 + ty * 8 + i) * 1536 + col0 + tx * 8;
        *(float4*)(p)     = v0;
        *(float4*)(p + 4) = v1;
    }
}

// ---------------------------------------------------------------------------
// RoPE + head split: K = rope(k), Q = rope(v), V = v ; layout [B,H,T,D]
// ---------------------------------------------------------------------------
__global__ __launch_bounds__(256) void rope_split(const float* __restrict__ cosb,
                                                  const float* __restrict__ sinb) {
    int idx = blockIdx.x * 256 + threadIdx.x;        // < B*T*H*32 = 1572864
    int d2 = idx & 31;
    int h  = (idx >> 5) % 12;
    int t  = (idx / (32 * 12)) & 2047;
    int b  = idx / (32 * 12 * 2048);
    int m  = b * 2048 + t;

    float2 kk = *(const float2*)(g_kv + m * 1536 + h * 64 + 2 * d2);
    float2 vv = *(const float2*)(g_kv + m * 1536 + 768 + h * 64 + 2 * d2);
    float c = cosb[t * 32 + d2];
    float s = sinb[t * 32 + d2];

    int o = ((b * 12 + h) * 2048 + t) * 64 + 2 * d2;
    *(float2*)(g_K + o) = make_float2(kk.x * c - kk.y * s, kk.x * s + kk.y * c);
    *(float2*)(g_Q + o) = make_float2(vv.x * c - vv.y * s, vv.x * s + vv.y * c);
    *(float2*)(g_V + o) = vv;
}

// ---------------------------------------------------------------------------
// Flash attention, causal. One CTA per (b, h, 64-row q tile). 256 thr, 4x4 micro.
// Q/K stored transposed [d][r] with float4 XOR swizzle -> conflict-free compute.
// P reuses K's smem buffer. Smem = 3 * 16KB = 48KB.
// ---------------------------------------------------------------------------
__global__ __launch_bounds__(256) void flash_attn() {
    const int qt = blockIdx.x;     // 0..31
    const int h  = blockIdx.y;
    const int b  = blockIdx.z;
    const int tid = threadIdx.x;
    const int tx = tid & 15, ty = tid >> 4;

    __shared__ float Qs [64][64];  // swizzled transposed
    __shared__ float KPs[64][64];  // K swizzled transposed, then P row-major
    __shared__ float Vs [64][64];  // row-major [j][d]

    const int bh = b * H_ + h;
    const float* Qg = g_Q + (bh * T_ + qt * 64) * 64;

    // Load Q tile (swizzled transpose)
#pragma unroll
    for (int it = 0; it < 4; it++) {
        int idx = tid + it * 256;
        int r = idx >> 4, d4 = (idx & 15) << 2;
        float4 q = *(const float4*)(Qg + r * 64 + d4);
        float qa[4] = {q.x, q.y, q.z, q.w};
#pragma unroll
        for (int j = 0; j < 4; j++) {
            int d = d4 + j;
            int c4 = ((r >> 2) ^ (d & 15)) << 2;
            Qs[d][c4 | (r & 3)] = qa[j];
        }
    }

    float m_i[4], l_i[4], o[4][4];
#pragma unroll
    for (int i = 0; i < 4; i++) {
        m_i[i] = -1e30f; l_i[i] = 0.0f;
#pragma unroll
        for (int n = 0; n < 4; n++) o[i][n] = 0.0f;
    }

    for (int kt = 0; kt <= qt; kt++) {
        __syncthreads();   // prev iter done with KPs(P) and Vs
        const float* Kg = g_K + (bh * T_ + kt * 64) * 64;
        const float* Vg = g_V + (bh * T_ + kt * 64) * 64;
#pragma unroll
        for (int it = 0; it < 4; it++) {
            int idx = tid + it * 256;
            int r = idx >> 4, d4 = (idx & 15) << 2;
            float4 kx = *(const float4*)(Kg + r * 64 + d4);
            float ka[4] = {kx.x, kx.y, kx.z, kx.w};
#pragma unroll
            for (int j = 0; j < 4; j++) {
                int d = d4 + j;
                int c4 = ((r >> 2) ^ (d & 15)) << 2;
                KPs[d][c4 | (r & 3)] = ka[j];
            }
            *(float4*)(&Vs[r][d4]) = *(const float4*)(Vg + r * 64 + d4);
        }
        __syncthreads();

        // S = Q K^T (4x4 per thread)
        float s[4][4];
#pragma unroll
        for (int i = 0; i < 4; i++)
#pragma unroll
            for (int j = 0; j < 4; j++) s[i][j] = 0.0f;

#pragma unroll 16
        for (int d = 0; d < 64; d++) {
            float4 q4 = *(const float4*)(&Qs [d][(ty ^ (d & 15)) << 2]);
            float4 k4 = *(const float4*)(&KPs[d][(tx ^ (d & 15)) << 2]);
            float qa[4] = {q4.x, q4.y, q4.z, q4.w};
            float ka[4] = {k4.x, k4.y, k4.z, k4.w};
#pragma unroll
            for (int i = 0; i < 4; i++)
#pragma unroll
                for (int j = 0; j < 4; j++) s[i][j] += qa[i] * ka[j];
        }

        // scale + causal mask (diag tile only)
        if (kt == qt) {
#pragma unroll
            for (int i = 0; i < 4; i++)
#pragma unroll
                for (int j = 0; j < 4; j++)
                    s[i][j] = (4 * tx + j > 4 * ty + i) ? -1e30f
                                                        : s[i][j] * 0.125f;
        } else {
#pragma unroll
            for (int i = 0; i < 4; i++)
#pragma unroll
                for (int j = 0; j < 4; j++) s[i][j] *= 0.125f;
        }

        // online softmax update
        float corr[4];
#pragma unroll
        for (int i = 0; i < 4; i++) {
            float rm = fmaxf(fmaxf(s[i][0], s[i][1]), fmaxf(s[i][2], s[i][3]));
#pragma unroll
            for (int msk = 8; msk; msk >>= 1)
                rm = fmaxf(rm, __shfl_xor_sync(0xffffffffu, rm, msk, 32));
            float mn = fmaxf(m_i[i], rm);
            corr[i] = __expf(m_i[i] - mn);
            m_i[i] = mn;
#pragma unroll
            for (int j = 0; j < 4; j++) s[i][j] = __expf(s[i][j] - mn);
            float rs = s[i][0] + s[i][1] + s[i][2] + s[i][3];
#pragma unroll
            for (int msk = 8; msk; msk >>= 1)
                rs += __shfl_xor_sync(0xffffffffu, rs, msk, 32);
            l_i[i] = l_i[i] * corr[i] + rs;
#pragma unroll
            for (int n = 0; n < 4; n++) o[i][n] *= corr[i];
        }

        __syncthreads();   // everyone done reading K from KPs
#pragma unroll
        for (int i = 0; i < 4; i++)
            *(float4*)(&KPs[4 * ty + i][4 * tx]) =
                make_float4(s[i][0], s[i][1], s[i][2], s[i][3]);
        __syncthreads();

        // O += P V  (4x4 per thread; P broadcast, V conflict-free float4)
#pragma unroll 4
        for (int j4 = 0; j4 < 16; j4++) {
            float pa[4][4];
#pragma unroll
            for (int i = 0; i < 4; i++) {
                float4 t4 = *(const float4*)(&KPs[4 * ty + i][4 * j4]);
                pa[i][0] = t4.x; pa[i][1] = t4.y; pa[i][2] = t4.z; pa[i][3] = t4.w;
            }
#pragma unroll
            for (int jj = 0; jj < 4; jj++) {
                float4 v4 = *(const float4*)(&Vs[4 * j4 + jj][4 * tx]);
                float va[4] = {v4.x, v4.y, v4.z, v4.w};
#pragma unroll
                for (int i = 0; i < 4; i++)
#pragma unroll
                    for (int n = 0; n < 4; n++) o[i][n] += pa[i][jj] * va[n];
            }
        }
    }

    float* Og = g_O + (bh * T_ + qt * 64) * 64;
#pragma unroll
    for (int i = 0; i < 4; i++) {
        float inv = 1.0f / l_i[i];
        *(float4*)(Og + (4 * ty + i) * 64 + 4 * tx) =
            make_float4(o[i][0] * inv, o[i][1] * inv, o[i][2] * inv, o[i][3] * inv);
    }
}

// ---------------------------------------------------------------------------
// Output projection: out[4096,768] = O(merged heads) @ W_proj + b_proj
// Head-merge transpose folded into A-tile indexing.
// ---------------------------------------------------------------------------
__global__ __launch_bounds__(256) void gemm_proj(const float* __restrict__ W,
                                                 const float* __restrict__ bias,
                                                 float* __restrict__ out) {
    __shared__ float As[16][128];
    __shared__ float Bs[16][128];
    const int tid = threadIdx.x;
    const int tx = tid & 15, ty = tid >> 4;
    const int row0 = blockIdx.y * 128;
    const int col0 = blockIdx.x * 128;

    float acc[8][8];
#pragma unroll
    for (int i = 0; i < 8; i++)
#pragma unroll
        for (int j = 0; j < 8; j++) acc[i][j] = 0.0f;

    for (int k0 = 0; k0 < 768; k0 += 16) {
        const int h = k0 >> 6;          // K-tile lies within one head (16 | 64)
        const int koff = k0 & 63;
#pragma unroll
        for (int it = 0; it < 2; it++) {
            int f = tid + it * 256;
            int r = f >> 2, c4 = (f & 3) << 2;
            int m = row0 + r;
            int b = m >> 11, t = m & 2047;
            float4 a = *(const float4*)(g_O + ((b * 12 + h) * 2048 + t) * 64
                                            + koff + c4);
            As[c4 + 0][r] = a.x; As[c4 + 1][r] = a.y;
            As[c4 + 2][r] = a.z; As[c4 + 3][r] = a.w;
        }
#pragma unroll
        for (int it = 0; it < 2; it++) {
            int f = tid + it * 256;
            int r = f >> 5, c4 = (f & 31) << 2;
            *(float4*)(&Bs[r][c4]) =
                *(const float4*)(W + (k0 + r) * 768 + col0 + c4);
        }
        __syncthreads();
#pragma unroll
        for (int k = 0; k < 16; k++) {
            float ra[8], rb[8];
            *(float4*)(ra)     = *(const float4*)(&As[k][ty * 8]);
            *(float4*)(ra + 4) = *(const float4*)(&As[k][ty * 8 + 4]);
            *(float4*)(rb)     = *(const float4*)(&Bs[k][tx * 8]);
            *(float4*)(rb + 4) = *(const float4*)(&Bs[k][tx * 8 + 4]);
#pragma unroll
            for (int i = 0; i < 8; i++)
#pragma unroll
                for (int j = 0; j < 8; j++) acc[i][j] += ra[i] * rb[j];
        }
        __syncthreads();
    }
#pragma unroll
    for (int i = 0; i < 8; i++) {
        int m = row0 + ty * 8 + i;
        int n = col0 + tx * 8;
        float4 v0 = make_float4(acc[i][0] + bias[n + 0], acc[i][1] + bias[n + 1],
                                acc[i][2] + bias[n + 2], acc[i][3] + bias[n + 3]);
        float4 v1 = make_float4(acc[i][4] + bias[n + 4], acc[i][5] + bias[n + 5],
                                acc[i][6] + bias[n + 6], acc[i][7] + bias[n + 7]);
        *(float4*)(out + m * 768 + n)     = v0;
        *(float4*)(out + m * 768 + n + 4) = v1;
    }
}

// ---------------------------------------------------------------------------
extern "C" void kernel_launch(void* const* d_in, const int* in_sizes, int n_in,
                              void* d_out, int out_size) {
    const float* x      = (const float*)d_in[0];
    const float* r_cos  = (const float*)d_in[1];
    const float* r_sin  = (const float*)d_in[2];
    const float* W_att  = (const float*)d_in[3];
    const float* W_proj = (const float*)d_in[4];
    const float* b_proj = (const float*)d_in[5];
    float* out = (float*)d_out;

    gemm_qkv <<<dim3(12, 32), 256>>>(x, W_att);
    rope_split<<<6144, 256>>>(r_cos, r_sin);
    flash_attn<<<dim3(32, 12, 2), 256>>>();
    gemm_proj<<<dim3(6, 32), 256>>>(W_proj, b_proj, out);
}

// round 7
// speedup vs baseline: 1.3968x; 1.3968x over previous
#include <cuda_runtime.h>
#include <cstdint>

// Problem: B=2, T=2048, C=768, H=12, D=64
// Reference (with faithful source bug q := rope(v)):
//   qkv = x @ W_att ; k = qkv[:, :768], v = qkv[:, 1536:2304] (q chunk UNUSED)
//   K = rope(k), Q = rope(v), V = v ; O = causal_softmax(Q K^T / 8) V
//   out = O(merged) @ W_proj + b_proj
//
// R5: both GEMMs on TF32 tensor cores (mma.sync m16n8k8), flash fp32 unchanged.

#define T_ 2048
#define C_ 768
#define H_ 12
#define D_ 64
#define B_ 2
#define KP 136   // smem row pitch (words): conflict-free fragment loads

__device__ float g_kv[4096 * 1536];               // [B*T, 2C]: k chunk | v chunk
__device__ float g_Q [B_ * H_ * T_ * D_];
__device__ float g_K [B_ * H_ * T_ * D_];
__device__ float g_V [B_ * H_ * T_ * D_];
__device__ float g_O [B_ * H_ * T_ * D_];

__device__ __forceinline__ uint32_t f2tf32(float x) {
    uint32_t r;
    asm("cvt.rna.tf32.f32 %0, %1;" : "=r"(r) : "f"(x));
    return r;
}

__device__ __forceinline__ void mma_tf32(float c[4], const uint32_t a[4],
                                         const uint32_t b[2]) {
    asm volatile(
        "mma.sync.aligned.m16n8k8.row.col.f32.tf32.tf32.f32 "
        "{%0,%1,%2,%3}, {%4,%5,%6,%7}, {%8,%9}, {%0,%1,%2,%3};\n"
        : "+f"(c[0]), "+f"(c[1]), "+f"(c[2]), "+f"(c[3])
        : "r"(a[0]), "r"(a[1]), "r"(a[2]), "r"(a[3]), "r"(b[0]), "r"(b[1]));
}

// ---------------------------------------------------------------------------
// TF32 QKV GEMM (k & v chunks only): g_kv[4096,1536] = x[4096,768] @ W_att cols
// logical col n -> W_att col (n < 768 ? n : n + 768)
// ---------------------------------------------------------------------------
__global__ __launch_bounds__(256, 2) void gemm_qkv(const float* __restrict__ A,
                                                   const float* __restrict__ W) {
    __shared__ uint32_t As[16][KP];   // [k][m] tf32
    __shared__ uint32_t Bs[16][KP];   // [k][n] tf32
    const int tid = threadIdx.x;
    const int wid = tid >> 5, lane = tid & 31;
    const int gID = lane >> 2, tig = lane & 3;
    const int warp_m = wid >> 2, warp_n = wid & 3;   // 2 x 4 warps
    const int row0 = blockIdx.y * 128;
    const int col0 = blockIdx.x * 128;
    const int wcol0 = (col0 < 768) ? col0 : col0 + 768;

    float acc[4][4][4];
#pragma unroll
    for (int mt = 0; mt < 4; mt++)
#pragma unroll
        for (int nt = 0; nt < 4; nt++)
#pragma unroll
            for (int r = 0; r < 4; r++) acc[mt][nt][r] = 0.0f;

    for (int k0 = 0; k0 < 768; k0 += 16) {
#pragma unroll
        for (int it = 0; it < 2; it++) {             // A: 128m x 16k
            int f = tid + it * 256;
            int r = f >> 2, c4 = (f & 3) << 2;
            float4 a = *(const float4*)(A + (row0 + r) * 768 + k0 + c4);
            As[c4 + 0][r] = f2tf32(a.x); As[c4 + 1][r] = f2tf32(a.y);
            As[c4 + 2][r] = f2tf32(a.z); As[c4 + 3][r] = f2tf32(a.w);
        }
#pragma unroll
        for (int it = 0; it < 2; it++) {             // B: 16k x 128n
            int f = tid + it * 256;
            int r = f >> 5, c4 = (f & 31) << 2;
            float4 b = *(const float4*)(W + (k0 + r) * 2304 + wcol0 + c4);
            Bs[r][c4 + 0] = f2tf32(b.x); Bs[r][c4 + 1] = f2tf32(b.y);
            Bs[r][c4 + 2] = f2tf32(b.z); Bs[r][c4 + 3] = f2tf32(b.w);
        }
        __syncthreads();
#pragma unroll
        for (int kk = 0; kk < 16; kk += 8) {
            uint32_t af[4][4], bf[4][2];
#pragma unroll
            for (int mt = 0; mt < 4; mt++) {
                int m = warp_m * 64 + mt * 16;
                af[mt][0] = As[kk + tig    ][m + gID    ];
                af[mt][1] = As[kk + tig    ][m + gID + 8];
                af[mt][2] = As[kk + tig + 4][m + gID    ];
                af[mt][3] = As[kk + tig + 4][m + gID + 8];
            }
#pragma unroll
            for (int nt = 0; nt < 4; nt++) {
                int n = warp_n * 32 + nt * 8;
                bf[nt][0] = Bs[kk + tig    ][n + gID];
                bf[nt][1] = Bs[kk + tig + 4][n + gID];
            }
#pragma unroll
            for (int mt = 0; mt < 4; mt++)
#pragma unroll
                for (int nt = 0; nt < 4; nt++)
                    mma_tf32(acc[mt][nt], af[mt], bf[nt]);
        }
        __syncthreads();
    }
#pragma unroll
    for (int mt = 0; mt < 4; mt++)
#pragma unroll
        for (int nt = 0; nt < 4; nt++) {
            int m = row0 + warp_m * 64 + mt * 16 + gID;
            int n = col0 + warp_n * 32 + nt * 8 + 2 * tig;
            *(float2*)(g_kv + m * 1536 + n) =
                make_float2(acc[mt][nt][0], acc[mt][nt][1]);
            *(float2*)(g_kv + (m + 8) * 1536 + n) =
                make_float2(acc[mt][nt][2], acc[mt][nt][3]);
        }
}

// ---------------------------------------------------------------------------
// RoPE + head split: K = rope(k), Q = rope(v), V = v ; layout [B,H,T,D]
// ---------------------------------------------------------------------------
__global__ __launch_bounds__(256) void rope_split(const float* __restrict__ cosb,
                                                  const float* __restrict__ sinb) {
    int idx = blockIdx.x * 256 + threadIdx.x;        // < B*T*H*32 = 1572864
    int d2 = idx & 31;
    int h  = (idx >> 5) % 12;
    int t  = (idx / (32 * 12)) & 2047;
    int b  = idx / (32 * 12 * 2048);
    int m  = b * 2048 + t;

    float2 kk = *(const float2*)(g_kv + m * 1536 + h * 64 + 2 * d2);
    float2 vv = *(const float2*)(g_kv + m * 1536 + 768 + h * 64 + 2 * d2);
    float c = cosb[t * 32 + d2];
    float s = sinb[t * 32 + d2];

    int o = ((b * 12 + h) * 2048 + t) * 64 + 2 * d2;
    *(float2*)(g_K + o) = make_float2(kk.x * c - kk.y * s, kk.x * s + kk.y * c);
    *(float2*)(g_Q + o) = make_float2(vv.x * c - vv.y * s, vv.x * s + vv.y * c);
    *(float2*)(g_V + o) = vv;
}

// ---------------------------------------------------------------------------
// Flash attention, causal. One CTA per (b, h, 64-row q tile). 256 thr, 4x4 micro.
// Q/K stored transposed [d][r] with float4 XOR swizzle -> conflict-free compute.
// P reuses K's smem buffer. Smem = 3 * 16KB = 48KB.
// ---------------------------------------------------------------------------
__global__ __launch_bounds__(256) void flash_attn() {
    const int qt = blockIdx.x;     // 0..31
    const int h  = blockIdx.y;
    const int b  = blockIdx.z;
    const int tid = threadIdx.x;
    const int tx = tid & 15, ty = tid >> 4;

    __shared__ float Qs [64][64];  // swizzled transposed
    __shared__ float KPs[64][64];  // K swizzled transposed, then P row-major
    __shared__ float Vs [64][64];  // row-major [j][d]

    const int bh = b * H_ + h;
    const float* Qg = g_Q + (bh * T_ + qt * 64) * 64;

#pragma unroll
    for (int it = 0; it < 4; it++) {
        int idx = tid + it * 256;
        int r = idx >> 4, d4 = (idx & 15) << 2;
        float4 q = *(const float4*)(Qg + r * 64 + d4);
        float qa[4] = {q.x, q.y, q.z, q.w};
#pragma unroll
        for (int j = 0; j < 4; j++) {
            int d = d4 + j;
            int c4 = ((r >> 2) ^ (d & 15)) << 2;
            Qs[d][c4 | (r & 3)] = qa[j];
        }
    }

    float m_i[4], l_i[4], o[4][4];
#pragma unroll
    for (int i = 0; i < 4; i++) {
        m_i[i] = -1e30f; l_i[i] = 0.0f;
#pragma unroll
        for (int n = 0; n < 4; n++) o[i][n] = 0.0f;
    }

    for (int kt = 0; kt <= qt; kt++) {
        __syncthreads();   // prev iter done with KPs(P) and Vs
        const float* Kg = g_K + (bh * T_ + kt * 64) * 64;
        const float* Vg = g_V + (bh * T_ + kt * 64) * 64;
#pragma unroll
        for (int it = 0; it < 4; it++) {
            int idx = tid + it * 256;
            int r = idx >> 4, d4 = (idx & 15) << 2;
            float4 kx = *(const float4*)(Kg + r * 64 + d4);
            float ka[4] = {kx.x, kx.y, kx.z, kx.w};
#pragma unroll
            for (int j = 0; j < 4; j++) {
                int d = d4 + j;
                int c4 = ((r >> 2) ^ (d & 15)) << 2;
                KPs[d][c4 | (r & 3)] = ka[j];
            }
            *(float4*)(&Vs[r][d4]) = *(const float4*)(Vg + r * 64 + d4);
        }
        __syncthreads();

        float s[4][4];
#pragma unroll
        for (int i = 0; i < 4; i++)
#pragma unroll
            for (int j = 0; j < 4; j++) s[i][j] = 0.0f;

#pragma unroll 16
        for (int d = 0; d < 64; d++) {
            float4 q4 = *(const float4*)(&Qs [d][(ty ^ (d & 15)) << 2]);
            float4 k4 = *(const float4*)(&KPs[d][(tx ^ (d & 15)) << 2]);
            float qa[4] = {q4.x, q4.y, q4.z, q4.w};
            float ka[4] = {k4.x, k4.y, k4.z, k4.w};
#pragma unroll
            for (int i = 0; i < 4; i++)
#pragma unroll
                for (int j = 0; j < 4; j++) s[i][j] += qa[i] * ka[j];
        }

        if (kt == qt) {
#pragma unroll
            for (int i = 0; i < 4; i++)
#pragma unroll
                for (int j = 0; j < 4; j++)
                    s[i][j] = (4 * tx + j > 4 * ty + i) ? -1e30f
                                                        : s[i][j] * 0.125f;
        } else {
#pragma unroll
            for (int i = 0; i < 4; i++)
#pragma unroll
                for (int j = 0; j < 4; j++) s[i][j] *= 0.125f;
        }

        float corr[4];
#pragma unroll
        for (int i = 0; i < 4; i++) {
            float rm = fmaxf(fmaxf(s[i][0], s[i][1]), fmaxf(s[i][2], s[i][3]));
#pragma unroll
            for (int msk = 8; msk; msk >>= 1)
                rm = fmaxf(rm, __shfl_xor_sync(0xffffffffu, rm, msk, 32));
            float mn = fmaxf(m_i[i], rm);
            corr[i] = __expf(m_i[i] - mn);
            m_i[i] = mn;
#pragma unroll
            for (int j = 0; j < 4; j++) s[i][j] = __expf(s[i][j] - mn);
            float rs = s[i][0] + s[i][1] + s[i][2] + s[i][3];
#pragma unroll
            for (int msk = 8; msk; msk >>= 1)
                rs += __shfl_xor_sync(0xffffffffu, rs, msk, 32);
            l_i[i] = l_i[i] * corr[i] + rs;
#pragma unroll
            for (int n = 0; n < 4; n++) o[i][n] *= corr[i];
        }

        __syncthreads();   // everyone done reading K from KPs
#pragma unroll
        for (int i = 0; i < 4; i++)
            *(float4*)(&KPs[4 * ty + i][4 * tx]) =
                make_float4(s[i][0], s[i][1], s[i][2], s[i][3]);
        __syncthreads();

#pragma unroll 4
        for (int j4 = 0; j4 < 16; j4++) {
            float pa[4][4];
#pragma unroll
            for (int i = 0; i < 4; i++) {
                float4 t4 = *(const float4*)(&KPs[4 * ty + i][4 * j4]);
                pa[i][0] = t4.x; pa[i][1] = t4.y; pa[i][2] = t4.z; pa[i][3] = t4.w;
            }
#pragma unroll
            for (int jj = 0; jj < 4; jj++) {
                float4 v4 = *(const float4*)(&Vs[4 * j4 + jj][4 * tx]);
                float va[4] = {v4.x, v4.y, v4.z, v4.w};
#pragma unroll
                for (int i = 0; i < 4; i++)
#pragma unroll
                    for (int n = 0; n < 4; n++) o[i][n] += pa[i][jj] * va[n];
            }
        }
    }

    float* Og = g_O + (bh * T_ + qt * 64) * 64;
#pragma unroll
    for (int i = 0; i < 4; i++) {
        float inv = 1.0f / l_i[i];
        *(float4*)(Og + (4 * ty + i) * 64 + 4 * tx) =
            make_float4(o[i][0] * inv, o[i][1] * inv, o[i][2] * inv, o[i][3] * inv);
    }
}

// ---------------------------------------------------------------------------
// TF32 output projection: out[4096,768] = O(head-merged) @ W_proj + b_proj
// Head-merge transpose folded into A-tile gather.
// ---------------------------------------------------------------------------
__global__ __launch_bounds__(256, 2) void gemm_proj(const float* __restrict__ W,
                                                    const float* __restrict__ bias,
                                                    float* __restrict__ out) {
    __shared__ uint32_t As[16][KP];
    __shared__ uint32_t Bs[16][KP];
    const int tid = threadIdx.x;
    const int wid = tid >> 5, lane = tid & 31;
    const int gID = lane >> 2, tig = lane & 3;
    const int warp_m = wid >> 2, warp_n = wid & 3;
    const int row0 = blockIdx.y * 128;
    const int col0 = blockIdx.x * 128;

    float acc[4][4][4];
#pragma unroll
    for (int mt = 0; mt < 4; mt++)
#pragma unroll
        for (int nt = 0; nt < 4; nt++)
#pragma unroll
            for (int r = 0; r < 4; r++) acc[mt][nt][r] = 0.0f;

    for (int k0 = 0; k0 < 768; k0 += 16) {
        const int h = k0 >> 6;          // K-tile lies inside one head (16 | 64)
        const int koff = k0 & 63;
#pragma unroll
        for (int it = 0; it < 2; it++) {
            int f = tid + it * 256;
            int r = f >> 2, c4 = (f & 3) << 2;
            int m = row0 + r;
            int b = m >> 11, t = m & 2047;
            float4 a = *(const float4*)(g_O + ((b * 12 + h) * 2048 + t) * 64
                                            + koff + c4);
            As[c4 + 0][r] = f2tf32(a.x); As[c4 + 1][r] = f2tf32(a.y);
            As[c4 + 2][r] = f2tf32(a.z); As[c4 + 3][r] = f2tf32(a.w);
        }
#pragma unroll
        for (int it = 0; it < 2; it++) {
            int f = tid + it * 256;
            int r = f >> 5, c4 = (f & 31) << 2;
            float4 b = *(const float4*)(W + (k0 + r) * 768 + col0 + c4);
            Bs[r][c4 + 0] = f2tf32(b.x); Bs[r][c4 + 1] = f2tf32(b.y);
            Bs[r][c4 + 2] = f2tf32(b.z); Bs[r][c4 + 3] = f2tf32(b.w);
        }
        __syncthreads();
#pragma unroll
        for (int kk = 0; kk < 16; kk += 8) {
            uint32_t af[4][4], bf[4][2];
#pragma unroll
            for (int mt = 0; mt < 4; mt++) {
                int m = warp_m * 64 + mt * 16;
                af[mt][0] = As[kk + tig    ][m + gID    ];
                af[mt][1] = As[kk + tig    ][m + gID + 8];
                af[mt][2] = As[kk + tig + 4][m + gID    ];
                af[mt][3] = As[kk + tig + 4][m + gID + 8];
            }
#pragma unroll
            for (int nt = 0; nt < 4; nt++) {
                int n = warp_n * 32 + nt * 8;
                bf[nt][0] = Bs[kk + tig    ][n + gID];
                bf[nt][1] = Bs[kk + tig + 4][n + gID];
            }
#pragma unroll
            for (int mt = 0; mt < 4; mt++)
#pragma unroll
                for (int nt = 0; nt < 4; nt++)
                    mma_tf32(acc[mt][nt], af[mt], bf[nt]);
        }
        __syncthreads();
    }
#pragma unroll
    for (int mt = 0; mt < 4; mt++)
#pragma unroll
        for (int nt = 0; nt < 4; nt++) {
            int m = row0 + warp_m * 64 + mt * 16 + gID;
            int n = col0 + warp_n * 32 + nt * 8 + 2 * tig;
            float b0 = bias[n], b1 = bias[n + 1];
            *(float2*)(out + m * 768 + n) =
                make_float2(acc[mt][nt][0] + b0, acc[mt][nt][1] + b1);
            *(float2*)(out + (m + 8) * 768 + n) =
                make_float2(acc[mt][nt][2] + b0, acc[mt][nt][3] + b1);
        }
}

// ---------------------------------------------------------------------------
extern "C" void kernel_launch(void* const* d_in, const int* in_sizes, int n_in,
                              void* d_out, int out_size) {
    const float* x      = (const float*)d_in[0];
    const float* r_cos  = (const float*)d_in[1];
    const float* r_sin  = (const float*)d_in[2];
    const float* W_att  = (const float*)d_in[3];
    const float* W_proj = (const float*)d_in[4];
    const float* b_proj = (const float*)d_in[5];
    float* out = (float*)d_out;

    gemm_qkv <<<dim3(12, 32), 256>>>(x, W_att);
    rope_split<<<6144, 256>>>(r_cos, r_sin);
    flash_attn<<<dim3(32, 12, 2), 256>>>();
    gemm_proj<<<dim3(6, 32), 256>>>(W_proj, b_proj, out);
}